// round 1
// baseline (speedup 1.0000x reference)
#include <cuda_runtime.h>
#include <cstdint>

#define BB 32
#define TT 512
#define II 128
#define HH 1024
#define GG 4096
#define OO 128

#define NBLK 260
#define NTH 256
#define CHUNK 64

// ---------------- device scratch (no allocations allowed) ----------------
__device__ float Wp_ih0[II * GG];   // [k][n] permuted: n = j*4+g
__device__ float Wp_hh0[HH * GG];
__device__ float Wp_ih1[HH * GG];
__device__ float Wp_hh1[HH * GG];
__device__ float Wp_out[HH * OO];   // [k][o]
__device__ float bp0[GG];
__device__ float bp1[GG];
__device__ float h0s[2][BB][HH];    // layer0 hidden (double-buffered)
__device__ float h2s[2][BB][HH];    // layer1 hidden (double-buffered)
__device__ float c0s[BB][HH];
__device__ float c1s[BB][HH];
__device__ unsigned g_bar;

// ---------------- init: zero states + barrier ----------------
__global__ void init_kernel() {
    int idx = blockIdx.x * blockDim.x + threadIdx.x;
    int stride = gridDim.x * blockDim.x;
    float* p0 = &h0s[0][0][0];
    float* p1 = &h2s[0][0][0];
    for (int i = idx; i < 2 * BB * HH; i += stride) { p0[i] = 0.f; p1[i] = 0.f; }
    float* p2 = &c0s[0][0];
    float* p3 = &c1s[0][0];
    for (int i = idx; i < BB * HH; i += stride) { p2[i] = 0.f; p3[i] = 0.f; }
    if (idx == 0) g_bar = 0u;
}

// ---------------- prep: transpose + gate-permute weights ----------------
__global__ void prep_kernel(const float* __restrict__ Wih0, const float* __restrict__ Whh0,
                            const float* __restrict__ b0v, const float* __restrict__ Wih1,
                            const float* __restrict__ Whh1, const float* __restrict__ b1v,
                            const float* __restrict__ Wout) {
    const int S0 = II * GG;      // 524288
    const int S1 = HH * GG;      // 4194304
    const int S4 = HH * OO;      // 131072
    const int total = S0 + 3 * S1 + S4 + 2 * GG;
    int stride = gridDim.x * blockDim.x;
    for (int idx = blockIdx.x * blockDim.x + threadIdx.x; idx < total; idx += stride) {
        int r = idx;
        if (r < S0) {
            int k = r >> 12, n = r & (GG - 1);
            int g = n & 3, j = n >> 2;
            Wp_ih0[r] = Wih0[(g * HH + j) * II + k];
        } else if ((r -= S0) < S1) {
            int k = r >> 12, n = r & (GG - 1);
            int g = n & 3, j = n >> 2;
            Wp_hh0[r] = Whh0[(g * HH + j) * HH + k];
        } else if ((r -= S1) < S1) {
            int k = r >> 12, n = r & (GG - 1);
            int g = n & 3, j = n >> 2;
            Wp_ih1[r] = Wih1[(g * HH + j) * HH + k];
        } else if ((r -= S1) < S1) {
            int k = r >> 12, n = r & (GG - 1);
            int g = n & 3, j = n >> 2;
            Wp_hh1[r] = Whh1[(g * HH + j) * HH + k];
        } else if ((r -= S1) < S4) {
            int k = r >> 7, o = r & (OO - 1);
            Wp_out[r] = Wout[o * HH + k];
        } else if ((r -= S4) < GG) {
            int g = r & 3, j = r >> 2;
            bp0[r] = b0v[g * HH + j];
        } else {
            r -= GG;
            int g = r & 3, j = r >> 2;
            bp1[r] = b1v[g * HH + j];
        }
    }
}

// ---------------- packed fp32x2 FMA ----------------
#define FMA2(acc, a, b) asm("fma.rn.f32x2 %0, %1, %2, %0;" : "+l"(acc) : "l"(a), "l"(b))

__device__ __forceinline__ float sigf(float x) { return 1.0f / (1.0f + __expf(-x)); }

__device__ __forceinline__ float2 up64(unsigned long long v) {
    float2 f;
    f.x = __uint_as_float((unsigned)v);
    f.y = __uint_as_float((unsigned)(v >> 32));
    return f;
}

// ROLE 0 = layer0 step (K=128 x + 1024 h), ROLE 1 = layer1 step (K=1024+1024),
// ROLE 2 = output head (K=1024)
template <int ROLE>
__device__ __forceinline__ void do_pass(int p, int t, int cg, int tid,
                                        unsigned long long (*tile)[CHUNK][33],
                                        const float* __restrict__ x,
                                        const float* __restrict__ b_out,
                                        float* __restrict__ out) {
    const int ng = tid & 7;           // 8 column-quads of 4
    const int bg = (tid >> 3) & 15;   // 16 batch pairs
    const int ks = tid >> 7;          // k-split half
    const int b0 = bg * 2;
    const int colbase = cg * 32;
    const int n0 = colbase + ng * 4;
    const int par = p & 1, prev = par ^ 1;

    constexpr int K2 = (ROLE == 0) ? 576 : (ROLE == 1) ? 1024 : 512;
    constexpr int NCH = K2 / CHUNK;
    constexpr int WS = (ROLE == 2) ? OO : GG;

    const float* __restrict__ hA = &h0s[prev][0][0];
    const float* __restrict__ hB = &h2s[prev][0][0];

    unsigned long long a00 = 0, a01 = 0, a10 = 0, a11 = 0;

    for (int c = 0; c < NCH; ++c) {
        __syncthreads();
        // stage both k-slices' chunks into smem, transposed + lane-duplicated
        #pragma unroll
        for (int u = 0; u < (2 * CHUNK * 32) / NTH; ++u) {
            int idx = tid + u * NTH;
            int ii = idx & 63;
            int bb = (idx >> 6) & 31;
            int ss = idx >> 11;
            int k = ss * K2 + c * CHUNK + ii;
            float v;
            if (ROLE == 0)
                v = (k < II) ? __ldg(&x[(bb * TT + t) * II + k]) : __ldcg(&hA[bb * HH + (k - II)]);
            else if (ROLE == 1)
                v = (k < HH) ? __ldcg(&hA[bb * HH + k]) : __ldcg(&hB[bb * HH + (k - HH)]);
            else
                v = __ldcg(&hB[bb * HH + k]);
            unsigned ui = __float_as_uint(v);
            tile[ss][ii][bb] = (unsigned long long)ui | ((unsigned long long)ui << 32);
        }
        __syncthreads();

        int kb = ks * K2 + c * CHUNK;
        const float* W;
        if (ROLE == 0)
            W = (kb < II) ? (Wp_ih0 + (size_t)kb * GG) : (Wp_hh0 + (size_t)(kb - II) * GG);
        else if (ROLE == 1)
            W = (kb < HH) ? (Wp_ih1 + (size_t)kb * GG) : (Wp_hh1 + (size_t)(kb - HH) * GG);
        else
            W = Wp_out + (size_t)kb * OO;
        const float* wp = W + n0;

        #pragma unroll 8
        for (int i = 0; i < CHUNK; ++i) {
            ulonglong2 w = *reinterpret_cast<const ulonglong2*>(wp + (size_t)i * WS);
            unsigned long long t0 = tile[ks][i][b0];
            unsigned long long t1 = tile[ks][i][b0 + 1];
            FMA2(a00, w.x, t0);   // (n0,n1) x b0
            FMA2(a01, w.x, t1);   // (n0,n1) x b1
            FMA2(a10, w.y, t0);   // (n2,n3) x b0
            FMA2(a11, w.y, t1);   // (n2,n3) x b1
        }
    }

    // k-split reduction through smem (reuse tile)
    __syncthreads();
    float* red = reinterpret_cast<float*>(tile);
    {
        float2 f;
        f = up64(a00); red[tid * 8 + 0] = f.x; red[tid * 8 + 1] = f.y;
        f = up64(a01); red[tid * 8 + 2] = f.x; red[tid * 8 + 3] = f.y;
        f = up64(a10); red[tid * 8 + 4] = f.x; red[tid * 8 + 5] = f.y;
        f = up64(a11); red[tid * 8 + 6] = f.x; red[tid * 8 + 7] = f.y;
    }
    __syncthreads();
    if (ks == 0) {
        float s[8];
        #pragma unroll
        for (int q = 0; q < 8; ++q) s[q] = red[tid * 8 + q] + red[(tid + 128) * 8 + q];

        if (ROLE < 2) {
            const float* bp = (ROLE == 0) ? bp0 : bp1;
            float* cst = (ROLE == 0) ? &c0s[0][0] : &c1s[0][0];
            float* hdst = (ROLE == 0) ? &h0s[par][0][0] : &h2s[par][0][0];
            int j = n0 >> 2;
            float bi_ = bp[n0], bf_ = bp[n0 + 1], bg_ = bp[n0 + 2], bo_ = bp[n0 + 3];
            {   // batch b0: i=s0, f=s1, g=s4, o=s5
                float ig = s[0] + bi_, fg = s[1] + bf_, gg = s[4] + bg_, og = s[5] + bo_;
                float cold = cst[b0 * HH + j];
                float cn = sigf(fg) * cold + sigf(ig) * tanhf(gg);
                cst[b0 * HH + j] = cn;
                __stcg(&hdst[b0 * HH + j], sigf(og) * tanhf(cn));
            }
            {   // batch b0+1: i=s2, f=s3, g=s6, o=s7
                float ig = s[2] + bi_, fg = s[3] + bf_, gg = s[6] + bg_, og = s[7] + bo_;
                float cold = cst[(b0 + 1) * HH + j];
                float cn = sigf(fg) * cold + sigf(ig) * tanhf(gg);
                cst[(b0 + 1) * HH + j] = cn;
                __stcg(&hdst[(b0 + 1) * HH + j], sigf(og) * tanhf(cn));
            }
        } else {
            float w0 = b_out[n0], w1 = b_out[n0 + 1], w2 = b_out[n0 + 2], w3 = b_out[n0 + 3];
            float* o0 = out + ((size_t)b0 * TT + t) * OO + n0;
            o0[0] = s[0] + w0; o0[1] = s[1] + w1; o0[2] = s[4] + w2; o0[3] = s[5] + w3;
            float* o1 = out + ((size_t)(b0 + 1) * TT + t) * OO + n0;
            o1[0] = s[2] + w0; o1[1] = s[3] + w1; o1[2] = s[6] + w2; o1[3] = s[7] + w3;
        }
    }
}

// ---------------- persistent pipelined kernel ----------------
__global__ void __launch_bounds__(NTH, 2) lstm_kernel(const float* __restrict__ x,
                                                      const float* __restrict__ b_out,
                                                      float* __restrict__ out) {
    __shared__ unsigned long long tile[2][CHUNK][33];
    const int tid = threadIdx.x;
    const int bid = blockIdx.x;

    int role, cg;
    if (bid < 128)      { role = 0; cg = bid; }
    else if (bid < 256) { role = 1; cg = bid - 128; }
    else                { role = 2; cg = bid - 256; }

    for (int p = 0; p < TT + 2; ++p) {
        if (role == 0) {
            if (p < TT) do_pass<0>(p, p, cg, tid, tile, x, b_out, out);
        } else if (role == 1) {
            if (p >= 1 && p <= TT) do_pass<1>(p, p - 1, cg, tid, tile, x, b_out, out);
        } else {
            if (p >= 2) do_pass<2>(p, p - 2, cg, tid, tile, x, b_out, out);
        }
        // ---- grid barrier (all 260 blocks guaranteed co-resident) ----
        __threadfence();
        __syncthreads();
        if (tid == 0) {
            atomicAdd(&g_bar, 1u);
            unsigned target = (unsigned)(p + 1) * NBLK;
            while (*((volatile unsigned*)&g_bar) < target) __nanosleep(64);
        }
        __syncthreads();
    }
}

// ---------------- launch ----------------
extern "C" void kernel_launch(void* const* d_in, const int* in_sizes, int n_in,
                              void* d_out, int out_size) {
    const float* x     = (const float*)d_in[0];
    const float* Wih0  = (const float*)d_in[1];
    const float* Whh0  = (const float*)d_in[2];
    const float* b0v   = (const float*)d_in[3];
    const float* Wih1  = (const float*)d_in[4];
    const float* Whh1  = (const float*)d_in[5];
    const float* b1v   = (const float*)d_in[6];
    const float* Wout  = (const float*)d_in[7];
    const float* boutv = (const float*)d_in[8];
    float* out = (float*)d_out;

    init_kernel<<<256, 256>>>();
    prep_kernel<<<512, 256>>>(Wih0, Whh0, b0v, Wih1, Whh1, b1v, Wout);
    lstm_kernel<<<NBLK, NTH>>>(x, boutv, out);
}